// round 16
// baseline (speedup 1.0000x reference)
#include <cuda_runtime.h>
#include <math.h>

#define QF   64
#define DEG  8          // degree-7 Chebyshev, 8 coeffs per dim, 64 moments
#define DCAP 4096
#define PTSW 704        // points per warp (multiple of 32); 2841 warps -> 711 blocks

// Runtime-fit Chebyshev coefficients of Gx/Gy per q, and per-segment moments.
__device__ float g_cx[QF * DEG];
__device__ float g_cy[QF * DEG];
__device__ float g_M[DCAP * QF];     // [d][i*8+j]

// ── zero the moment buffer (1 MB) ───────────────────────────────────────────
__global__ void zeroM_kernel(int n4) {
    int i = blockIdx.x * blockDim.x + threadIdx.x;
    if (i < n4) reinterpret_cast<float4*>(g_M)[i] = make_float4(0.f, 0.f, 0.f, 0.f);
}

// ── fit deg-7 Chebyshev interpolants of exp(-(a(x-p))^2) on x=(u+1)/2 ───────
__global__ void coeff_kernel(const float* __restrict__ sp,
                             const float* __restrict__ isg) {
    const int q = threadIdx.x;
    if (q >= QF) return;
    for (int dim = 0; dim < 2; dim++) {
        const float pq = sp[dim * QF + q];
        const float aq = isg[dim * QF + q];
        float f[DEG];
        #pragma unroll
        for (int k = 0; k < DEG; k++) {
            const float u = cospif((k + 0.5f) / DEG);   // Chebyshev nodes
            const float z = aq * (0.5f * (u + 1.0f) - pq);
            f[k] = expf(-z * z);
        }
        float* dst = (dim ? g_cy : g_cx) + q * DEG;
        #pragma unroll
        for (int j = 0; j < DEG; j++) {
            float c = 0.f;
            #pragma unroll
            for (int k = 0; k < DEG; k++)
                c += f[k] * cospif(j * (k + 0.5f) / DEG);  // T_j at node k
            dst[j] = c * ((j == 0 ? 1.0f : 2.0f) / DEG);
        }
    }
}

// ── phase 1: per-segment Chebyshev moments ──────────────────────────────────
__device__ __forceinline__ void accum_point(float x, float y, float (&m)[QF]) {
    const float u = fmaf(2.f, x, -1.f);
    const float v = fmaf(2.f, y, -1.f);
    const float u2 = u + u, v2 = v + v;
    float Tx[DEG], Ty[DEG];
    Tx[0] = 1.f; Tx[1] = u;
    Ty[0] = 1.f; Ty[1] = v;
    #pragma unroll
    for (int i = 2; i < DEG; i++) {
        Tx[i] = fmaf(u2, Tx[i - 1], -Tx[i - 2]);
        Ty[i] = fmaf(v2, Ty[i - 1], -Ty[i - 2]);
    }
    #pragma unroll
    for (int i = 0; i < DEG; i++)
        #pragma unroll
        for (int j = 0; j < DEG; j++)
            m[i * DEG + j] = fmaf(Tx[i], Ty[j], m[i * DEG + j]);
}

// Warp-collective flush: 2 butterfly stages then 8-lane REDG per moment.
__device__ __forceinline__ void warp_flush(float (&m)[QF], int cur, int lane) {
    float* dst = g_M + cur * QF;
    const bool w = lane < 8;
    #pragma unroll
    for (int k = 0; k < QF; k++) {
        float s = m[k];
        s += __shfl_xor_sync(0xffffffffu, s, 16);
        s += __shfl_xor_sync(0xffffffffu, s, 8);
        if (w) atomicAdd(dst + k, s);   // lanes 0-7 hold sums of lanes ≡ l (mod 8)
        m[k] = 0.f;
    }
}

__global__ __launch_bounds__(128) void moment_kernel(
    const float2* __restrict__ xy,
    const int*    __restrict__ seg,
    int n)
{
    const unsigned FULL = 0xffffffffu;
    const int warp_id = blockIdx.x * (blockDim.x >> 5) + (threadIdx.x >> 5);
    const int lane    = threadIdx.x & 31;
    const int start   = warp_id * PTSW;
    if (start >= n) return;
    const int end = min(start + PTSW, n);

    float m[QF];
    #pragma unroll
    for (int k = 0; k < QF; k++) m[k] = 0.f;

    int cur = seg[start];    // warp-uniform current segment

    for (int p = start; p < end; p += 32) {
        const int  idx   = p + lane;
        const bool valid = idx < end;
        float2 c = make_float2(0.f, 0.f);
        int    s = cur;
        if (valid) { c = xy[idx]; s = seg[idx]; }   // coalesced

        if (__all_sync(FULL, s == cur)) {
            if (valid) accum_point(c.x, c.y, m);    // hot path: whole block uniform
        } else {
            // Rare: block crosses >=1 segment boundary. Process segments in
            // ascending order (sorted index); flush warp-collectively at each
            // transition so 'cur' stays warp-uniform.
            bool done = !valid;
            unsigned todo = __ballot_sync(FULL, !done);
            while (todo) {
                const int src  = __ffs(todo) - 1;
                const int segv = __shfl_sync(FULL, s, src);   // lowest pending seg
                if (segv != cur) { warp_flush(m, cur, lane); cur = segv; }
                if (!done && s == segv) { accum_point(c.x, c.y, m); done = true; }
                todo = __ballot_sync(FULL, !done);
            }
        }
    }
    warp_flush(m, cur, lane);
}

// ── phase 2: out[d][q] = cx(q)^T · M[d] · cy(q) ────────────────────────────
__global__ __launch_bounds__(256) void contract_kernel(float* __restrict__ out, int D) {
    const int q   = threadIdx.x & 63;
    const int sub = threadIdx.x >> 6;              // 4 segments per block
    const int d   = blockIdx.x * 4 + sub;
    __shared__ float sM[4][QF];
    if (d < D) sM[sub][q] = g_M[d * QF + q];
    __syncthreads();
    if (d >= D) return;

    float cx[DEG], cy[DEG];
    #pragma unroll
    for (int i = 0; i < DEG; i++) {
        cx[i] = g_cx[q * DEG + i];
        cy[i] = g_cy[q * DEG + i];
    }
    float r = 0.f;
    #pragma unroll
    for (int j = 0; j < DEG; j++) {
        float w = 0.f;
        #pragma unroll
        for (int i = 0; i < DEG; i++) w = fmaf(cx[i], sM[sub][i * DEG + j], w);
        r = fmaf(cy[j], w, r);
    }
    out[d * QF + q] = r;
}

extern "C" void kernel_launch(void* const* d_in, const int* in_sizes, int n_in,
                              void* d_out, int out_size) {
    const float2* xy  = (const float2*)d_in[0];
    const int*    seg = (const int*)   d_in[1];
    const float*  sp  = (const float*) d_in[2];
    const float*  isg = (const float*) d_in[3];
    float*        out = (float*)d_out;

    const int n = in_sizes[0] / 2;       // input is [N,2] float32
    const int D = out_size / QF;         // 4096

    const int m4 = (D * QF) >> 2;        // float4 count of g_M
    zeroM_kernel<<<(m4 + 255) / 256, 256>>>(m4);
    coeff_kernel<<<1, QF>>>(sp, isg);

    const int num_warps = (n + PTSW - 1) / PTSW;
    const int blocks    = (num_warps + 3) / 4;   // 4 warps / 128-thr block
    moment_kernel<<<blocks, 128>>>(xy, seg, n);

    contract_kernel<<<(D + 3) / 4, 256>>>(out, D);
}